// round 13
// baseline (speedup 1.0000x reference)
#include <cuda_runtime.h>
#include <math.h>

#define NB 8
#define NGT 100
#define NC 80
#define T_TOTAL 13343
#define NT 512              // threads per block: items <= 615 -> <= 2 volleys
#define MAXC 128            // max masked cells per box (analytic worst: 123)
#define IPC 5               // items per cell (16 classes each)
#define PADC 133            // psum row pitch (conflict-spread)

__device__ __forceinline__ float neg_term(float v) {
    float cp = fminf(fmaxf(v, 1e-6f), 1.0f - 1e-6f);
    return (0.75f * (cp * cp)) * (-__logf(1.0f - cp));
}

// ---------------------------------------------------------------------------
// One block per (batch, gt-box). Lazy s_neg over masked cells only.
// Phase 0: thread-per-cell mapping -> stc[]; cp[label]+regr loads issued into
//          registers (ride the scoreboard across phase 1).
// Phase 1: straight-line, TWO predicated 16-class items per thread -> all
//          class loads issued in ONE volley (no loop-carried serialization).
// Phase 2: thread-per-cell combine. Phase 3: f64 level reduce + numpy argmin.
// ---------------------------------------------------------------------------
__global__ __launch_bounds__(NT) void level_select_kernel(
        const float* __restrict__ cls,
        const float4* __restrict__ regr4,
        const float* __restrict__ gt,
        float* __restrict__ out) {
    const int   fdim_[5] = {100, 50, 25, 13, 7};
    const int   ls_[5]   = {0, 10000, 12500, 13125, 13294};
    const float st_[5]   = {8.f, 16.f, 32.f, 64.f, 128.f};

    int bn   = blockIdx.x;                 // b*100 + n
    int b    = bn / NGT;
    int tid  = threadIdx.x;
    int lane = tid & 31;
    int wid  = tid >> 5;

    __shared__ int    stc[MAXC];           // cell -> flat location t
    __shared__ float  psum[IPC * PADC];    // [item][cell] neg-focal partials
    __shared__ float  sval[MAXC];          // per-cell total loss
    __shared__ double lvl[5];

    const float* gbox = gt + (size_t)bn * 5;
    float b0 = __ldg(gbox + 0), b1 = __ldg(gbox + 1);
    float b2 = __ldg(gbox + 2), b3 = __ldg(gbox + 3);
    int   label = (int)__ldg(gbox + 4);

    if (!((fabsf(b0) + fabsf(b1) + fabsf(b2) + fabsf(b3)) > 0.0f)) {
        if (tid == 0) out[bn] = -1.0f;
        return;
    }

    const float*  clsb  = cls   + (size_t)b * T_TOTAL * NC;
    const float4* clsb4 = (const float4*)clsb;           // 20 quads per cell
    const float4* regb  = regr4 + (size_t)b * T_TOTAL;

    // all 5 center-sampling rects (exact f32 replica of the reference)
    int rx1[5], ry1[5], rnx[5], rcnt[5];
    #pragma unroll
    for (int k = 0; k < 5; k++) {
        float stride = st_[k];
        int   fw = fdim_[k];
        float pb0 = b0 / stride, pb1 = b1 / stride;
        float pb2 = b2 / stride, pb3 = b3 / stride;
        float cx = (pb0 + pb2) * 0.5f, cy = (pb1 + pb3) * 0.5f;
        float hw = ((pb2 - pb0) * 0.2f) * 0.5f;
        float hh = ((pb3 - pb1) * 0.2f) * 0.5f;
        int x1 = (int)fminf(fmaxf(floorf(cx - hw), 0.0f), (float)(fw - 1));
        int y1 = (int)fminf(fmaxf(floorf(cy - hh), 0.0f), (float)(fw - 1));
        int x2 = min(max((int)ceilf(cx + hw), x1 + 1), fw);
        int y2 = min(max((int)ceilf(cy + hh), y1 + 1), fw);
        rx1[k] = x1; ry1[k] = y1;
        rnx[k] = x2 - x1;
        rcnt[k] = (x2 - x1) * (y2 - y1);
    }
    int total = rcnt[0] + rcnt[1] + rcnt[2] + rcnt[3] + rcnt[4];

    // ---- Phase 0: per-cell mapping; issue label/regr loads early ----
    int   myl = -1, myx = 0, myy = 0;
    float cpl = 0.0f;
    float4 r  = make_float4(0.f, 0.f, 0.f, 0.f);
    if (tid < total) {
        int c = tid;
        #pragma unroll
        for (int k = 0; k < 5; k++)
            if (myl < 0) { if (c < rcnt[k]) myl = k; else c -= rcnt[k]; }
        int nx = rnx[myl];
        myx = rx1[myl] + c % nx;
        myy = ry1[myl] + c / nx;
        int t = ls_[myl] + myy * fdim_[myl] + myx;
        stc[tid] = t;
        cpl = clsb[(size_t)t * NC + label];     // in flight across phase 1
        r   = regb[t];                          // in flight across phase 1
    }
    __syncthreads();

    // ---- Phase 1: straight-line, two predicated items -> ONE load volley ----
    int items = total * IPC;                    // <= 615
    {
        int  i0 = tid,  i1 = tid + NT;
        bool p0 = i0 < items, p1 = i1 < items;
        int  c0 = 0, q0 = 0, c1 = 0, q1 = 0;
        const float4 *a0 = clsb4, *a1 = clsb4;
        if (p0) { c0 = i0 / IPC; q0 = i0 - c0 * IPC;
                  a0 = clsb4 + stc[c0] * (NC / 4) + q0 * 4; }
        if (p1) { c1 = i1 / IPC; q1 = i1 - c1 * IPC;
                  a1 = clsb4 + stc[c1] * (NC / 4) + q1 * 4; }
        float4 u0, u1, u2, u3, w0, w1, w2, w3;
        if (p0) { u0 = a0[0]; u1 = a0[1]; u2 = a0[2]; u3 = a0[3]; }
        if (p1) { w0 = a1[0]; w1 = a1[1]; w2 = a1[2]; w3 = a1[3]; }
        if (p0) {
            float s = ((neg_term(u0.x) + neg_term(u0.y)) + (neg_term(u0.z) + neg_term(u0.w)))
                    + ((neg_term(u1.x) + neg_term(u1.y)) + (neg_term(u1.z) + neg_term(u1.w)))
                    + ((neg_term(u2.x) + neg_term(u2.y)) + (neg_term(u2.z) + neg_term(u2.w)))
                    + ((neg_term(u3.x) + neg_term(u3.y)) + (neg_term(u3.z) + neg_term(u3.w)));
            psum[q0 * PADC + c0] = s;
        }
        if (p1) {
            float s = ((neg_term(w0.x) + neg_term(w0.y)) + (neg_term(w0.z) + neg_term(w0.w)))
                    + ((neg_term(w1.x) + neg_term(w1.y)) + (neg_term(w1.z) + neg_term(w1.w)))
                    + ((neg_term(w2.x) + neg_term(w2.y)) + (neg_term(w2.z) + neg_term(w2.w)))
                    + ((neg_term(w3.x) + neg_term(w3.y)) + (neg_term(w3.z) + neg_term(w3.w)));
            psum[q1 * PADC + c1] = s;
        }
    }
    __syncthreads();

    // ---- Phase 2: thread per cell (mapping + loads already in regs) ----
    if (tid < total) {
        float sneg = ((psum[0 * PADC + tid] + psum[1 * PADC + tid])
                   +  (psum[2 * PADC + tid] + psum[3 * PADC + tid]))
                   +   psum[4 * PADC + tid];

        float cp = fminf(fmaxf(cpl, 1e-6f), 1.0f - 1e-6f);
        float om = 1.0f - cp;
        float neg_lab = (0.75f * (cp * cp)) * (-logf(om));
        float pos_lab = (0.25f * (om * om)) * (-logf(cp));

        float stride = st_[myl];
        float sx = ((float)myx + 0.5f) * stride;
        float sy = ((float)myy + 0.5f) * stride;
        float tl = (sx - b0) * 0.25f, tt = (sy - b1) * 0.25f;
        float tr = (b2 - sx) * 0.25f, tb = (b3 - sy) * 0.25f;
        float t_area = (tl + tr) * (tt + tb);
        float p_area = (r.x + r.z) * (r.y + r.w);
        float wi = fminf(r.x, tl) + fminf(r.z, tr);
        float hi = fminf(r.y, tt) + fminf(r.w, tb);
        float ai = wi * hi;
        float un = t_area + p_area - ai;
        float iou = -logf((ai + 1.0f) / (un + 1.0f));  // NaN propagates

        sval[tid] = (sneg - neg_lab + pos_lab) + iou;
    }
    __syncthreads();

    // ---- Phase 3: warp w reduces level w's segment in f64 (fixed order) ----
    if (wid < 5) {
        int pre = 0;
        #pragma unroll
        for (int k = 0; k < 5; k++) if (k < wid) pre += rcnt[k];
        int cnt = rcnt[wid];
        double s = 0.0;
        for (int i = lane; i < cnt; i += 32) s += (double)sval[pre + i];
        #pragma unroll
        for (int o = 16; o; o >>= 1) s += __shfl_down_sync(0xffffffffu, s, o);
        if (lane == 0) lvl[wid] = s / (double)cnt;
    }
    __syncthreads();

    if (tid == 0) {
        // numpy/jax argmin fold: pick if v<best, or v is NaN and best isn't.
        int    best = 0;
        double bv   = lvl[0];
        #pragma unroll
        for (int k = 1; k < 5; k++) {
            double v = lvl[k];
            if ((v < bv) || ((v != v) && (bv == bv))) { bv = v; best = k; }
        }
        out[bn] = (float)best;
    }
}

extern "C" void kernel_launch(void* const* d_in, const int* in_sizes, int n_in,
                              void* d_out, int out_size) {
    const float* cls  = (const float*)d_in[0];   // (8, 13343, 80) f32
    const float* regr = (const float*)d_in[1];   // (8, 13343, 4)  f32
    // d_in[2] = feature_shapes (compile-time constants, unused)
    const float* gt   = (const float*)d_in[3];   // (8, 100, 5)    f32
    float* out = (float*)d_out;                  // (8, 100)       f32

    level_select_kernel<<<NB * NGT, NT>>>(cls, (const float4*)regr, gt, out);
}

// round 14
// speedup vs baseline: 2.4194x; 2.4194x over previous
#include <cuda_runtime.h>
#include <math.h>

#define NB 8
#define NGT 100
#define NC 80
#define T_TOTAL 13343
#define NT 256              // threads per block (R12 proven config)
#define MAXC 128            // max masked cells per box (analytic worst: 123)
#define IPC 5               // items per cell (16 classes each)
#define PADC 133            // psum row pitch (conflict-spread)

__device__ __forceinline__ float neg_term(float v) {
    float cp = fminf(fmaxf(v, 1e-6f), 1.0f - 1e-6f);
    return (0.75f * (cp * cp)) * (-__logf(1.0f - cp));
}

// ---------------------------------------------------------------------------
// One block per (batch, gt-box). Lazy s_neg over masked cells only.
// Rect math computed ONCE (threads 0..4, one level each) -> smem, instead of
// redundantly by all 256 threads (that preamble was ~half the issue budget).
// Phase 0: thread-per-cell mapping -> stc[]; cp[label]+regr loads in regs.
// Phase 1: (cell, 16-class item) grid-stride; 4 indep LDG.128 per item.
// Phase 2: thread-per-cell combine. Phase 3: f64 level reduce + numpy argmin.
// ---------------------------------------------------------------------------
__global__ __launch_bounds__(NT) void level_select_kernel(
        const float* __restrict__ cls,
        const float4* __restrict__ regr4,
        const float* __restrict__ gt,
        float* __restrict__ out) {
    const int   fdim_[5] = {100, 50, 25, 13, 7};
    const int   ls_[5]   = {0, 10000, 12500, 13125, 13294};
    const float st_[5]   = {8.f, 16.f, 32.f, 64.f, 128.f};

    int bn   = blockIdx.x;                 // b*100 + n
    int b    = bn / NGT;
    int tid  = threadIdx.x;
    int lane = tid & 31;
    int wid  = tid >> 5;

    __shared__ int    srx1[5], sry1[5], srnx[5], srcnt[5], spre[6];
    __shared__ int    stc[MAXC];           // cell -> flat location t
    __shared__ float  psum[IPC * PADC];    // [item][cell] neg-focal partials
    __shared__ float  sval[MAXC];          // per-cell total loss
    __shared__ double lvl[5];

    const float* gbox = gt + (size_t)bn * 5;
    float b0 = __ldg(gbox + 0), b1 = __ldg(gbox + 1);
    float b2 = __ldg(gbox + 2), b3 = __ldg(gbox + 3);
    int   label = (int)__ldg(gbox + 4);

    if (!((fabsf(b0) + fabsf(b1) + fabsf(b2) + fabsf(b3)) > 0.0f)) {
        if (tid == 0) out[bn] = -1.0f;
        return;
    }

    const float*  clsb  = cls   + (size_t)b * T_TOTAL * NC;
    const float4* clsb4 = (const float4*)clsb;           // 20 quads per cell
    const float4* regb  = regr4 + (size_t)b * T_TOTAL;

    // rect math ONCE: thread k (<5) computes level k's center-sampling rect
    // (exact f32 replica of the reference)
    if (tid < 5) {
        float stride = st_[tid];
        int   fw = fdim_[tid];
        float pb0 = b0 / stride, pb1 = b1 / stride;
        float pb2 = b2 / stride, pb3 = b3 / stride;
        float cx = (pb0 + pb2) * 0.5f, cy = (pb1 + pb3) * 0.5f;
        float hw = ((pb2 - pb0) * 0.2f) * 0.5f;
        float hh = ((pb3 - pb1) * 0.2f) * 0.5f;
        int x1 = (int)fminf(fmaxf(floorf(cx - hw), 0.0f), (float)(fw - 1));
        int y1 = (int)fminf(fmaxf(floorf(cy - hh), 0.0f), (float)(fw - 1));
        int x2 = min(max((int)ceilf(cx + hw), x1 + 1), fw);
        int y2 = min(max((int)ceilf(cy + hh), y1 + 1), fw);
        srx1[tid] = x1; sry1[tid] = y1;
        srnx[tid] = x2 - x1;
        srcnt[tid] = (x2 - x1) * (y2 - y1);
    }
    __syncthreads();

    if (tid == 0) {
        int acc = 0;
        #pragma unroll
        for (int k = 0; k < 5; k++) { spre[k] = acc; acc += srcnt[k]; }
        spre[5] = acc;
    }
    __syncthreads();
    int total = spre[5];

    // ---- Phase 0: per-cell mapping; issue label/regr loads early ----
    int   myl = 0, myx = 0, myy = 0;
    float cpl = 0.0f;
    float4 r  = make_float4(0.f, 0.f, 0.f, 0.f);
    if (tid < total) {
        // find level: largest k with spre[k] <= tid
        #pragma unroll
        for (int k = 1; k < 5; k++) if (tid >= spre[k]) myl = k;
        int c  = tid - spre[myl];
        int nx = srnx[myl];
        myx = srx1[myl] + c % nx;
        myy = sry1[myl] + c / nx;
        int t = ls_[myl] + myy * fdim_[myl] + myx;
        stc[tid] = t;
        cpl = clsb[(size_t)t * NC + label];     // in flight across phase 1
        r   = regb[t];                          // in flight across phase 1
    }
    __syncthreads();

    // ---- Phase 1: (cell, item) grid; 16 classes/item, 4 indep LDG.128 ----
    int items = total * IPC;                    // <= 615 -> <= 3 iterations
    for (int i = tid; i < items; i += NT) {
        int cell = i / IPC;
        int q    = i - cell * IPC;
        int t    = stc[cell];
        const float4* p = clsb4 + t * (NC / 4) + q * 4;
        float4 v0 = p[0], v1 = p[1], v2 = p[2], v3 = p[3];
        float s = ((neg_term(v0.x) + neg_term(v0.y)) + (neg_term(v0.z) + neg_term(v0.w)))
                + ((neg_term(v1.x) + neg_term(v1.y)) + (neg_term(v1.z) + neg_term(v1.w)))
                + ((neg_term(v2.x) + neg_term(v2.y)) + (neg_term(v2.z) + neg_term(v2.w)))
                + ((neg_term(v3.x) + neg_term(v3.y)) + (neg_term(v3.z) + neg_term(v3.w)));
        psum[q * PADC + cell] = s;
    }
    __syncthreads();

    // ---- Phase 2: thread per cell (mapping + loads already in regs) ----
    if (tid < total) {
        float sneg = ((psum[0 * PADC + tid] + psum[1 * PADC + tid])
                   +  (psum[2 * PADC + tid] + psum[3 * PADC + tid]))
                   +   psum[4 * PADC + tid];

        float cp = fminf(fmaxf(cpl, 1e-6f), 1.0f - 1e-6f);
        float om = 1.0f - cp;
        float neg_lab = (0.75f * (cp * cp)) * (-logf(om));
        float pos_lab = (0.25f * (om * om)) * (-logf(cp));

        float stride = st_[myl];
        float sx = ((float)myx + 0.5f) * stride;
        float sy = ((float)myy + 0.5f) * stride;
        float tl = (sx - b0) * 0.25f, tt = (sy - b1) * 0.25f;
        float tr = (b2 - sx) * 0.25f, tb = (b3 - sy) * 0.25f;
        float t_area = (tl + tr) * (tt + tb);
        float p_area = (r.x + r.z) * (r.y + r.w);
        float wi = fminf(r.x, tl) + fminf(r.z, tr);
        float hi = fminf(r.y, tt) + fminf(r.w, tb);
        float ai = wi * hi;
        float un = t_area + p_area - ai;
        float iou = -logf((ai + 1.0f) / (un + 1.0f));  // NaN propagates

        sval[tid] = (sneg - neg_lab + pos_lab) + iou;
    }
    __syncthreads();

    // ---- Phase 3: warp w reduces level w's segment in f64 (fixed order) ----
    if (wid < 5) {
        int pre = spre[wid];
        int cnt = srcnt[wid];
        double s = 0.0;
        for (int i = lane; i < cnt; i += 32) s += (double)sval[pre + i];
        #pragma unroll
        for (int o = 16; o; o >>= 1) s += __shfl_down_sync(0xffffffffu, s, o);
        if (lane == 0) lvl[wid] = s / (double)cnt;
    }
    __syncthreads();

    if (tid == 0) {
        // numpy/jax argmin fold: pick if v<best, or v is NaN and best isn't.
        int    best = 0;
        double bv   = lvl[0];
        #pragma unroll
        for (int k = 1; k < 5; k++) {
            double v = lvl[k];
            if ((v < bv) || ((v != v) && (bv == bv))) { bv = v; best = k; }
        }
        out[bn] = (float)best;
    }
}

extern "C" void kernel_launch(void* const* d_in, const int* in_sizes, int n_in,
                              void* d_out, int out_size) {
    const float* cls  = (const float*)d_in[0];   // (8, 13343, 80) f32
    const float* regr = (const float*)d_in[1];   // (8, 13343, 4)  f32
    // d_in[2] = feature_shapes (compile-time constants, unused)
    const float* gt   = (const float*)d_in[3];   // (8, 100, 5)    f32
    float* out = (float*)d_out;                  // (8, 100)       f32

    level_select_kernel<<<NB * NGT, NT>>>(cls, (const float4*)regr, gt, out);
}